// round 17
// baseline (speedup 1.0000x reference)
#include <cuda_runtime.h>
#include <cstdint>

#define B 512
#define V 6890
#define NJ 24
#define NP 207
#define NJO 19
#define VC (V*3)            // 20670
#define VCP 20736           // padded vc stride = 162*128
#define KP 224              // padded K (218 real rows)

#define VERT_OFF 0
#define JNT_OFF  (B*V*3)              // 10583040
#define ROT_OFF  (JNT_OFF + B*NJO*3)  // 10612224

typedef unsigned long long ull;

// Scratch (__device__ globals: allocation-free rule)
__device__ float g_P[(size_t)KP*VCP];     // 18.6MB packed+padded [posedirs;shapes;template;0]
__device__ float g_pft2[KP*1024];         // [k][b*2+{0,1}] duplicated factor matrix
__device__ float g_Jdirs[11*NJ*3];
__device__ float g_A[B*NJ*12];            // relative transforms 3x4 row-major
__device__ float g_vposed[(size_t)B*VCP]; // 42.5MB v_posed (incl template)

// ---- packed f32x2 helpers --------------------------------------------------
__device__ __forceinline__ void ffma2(ull &d, ull a, ull b) {
    asm("fma.rn.f32x2 %0, %1, %2, %0;" : "+l"(d) : "l"(a), "l"(b));
}
__device__ __forceinline__ ull pack2(float x, float y) {
    ull r; asm("mov.b64 %0, {%1, %2};" : "=l"(r) : "f"(x), "f"(y)); return r;
}
__device__ __forceinline__ void unpack2(ull v, float &lo, float &hi) {
    asm("mov.b64 {%0, %1}, %2;" : "=f"(lo), "=f"(hi) : "l"(v));
}
__device__ __forceinline__ void cpasync16(uint32_t s, const void* g) {
    asm volatile("cp.async.cg.shared.global [%0], [%1], 16;" :: "r"(s), "l"(g));
}

// ---------------------------------------------------------------------------
// K0: pack P = [posedirs; shapes; v_template; zeros] into padded g_P
// ---------------------------------------------------------------------------
__global__ void k0_pack(const float* __restrict__ posedirs,
                        const float* __restrict__ shapes,
                        const float* __restrict__ v_template) {
    int idx = blockIdx.x * blockDim.x + threadIdx.x;
    if (idx >= KP*(VCP/4)) return;
    int k = idx / (VCP/4);
    int q = idx % (VCP/4);
    int gc = q * 4;
    float4 val = make_float4(0.f, 0.f, 0.f, 0.f);
    if (k < 218) {
        const float* src = (k < NP) ? posedirs + (size_t)k*VC
                         : (k < 217) ? shapes + (size_t)(k-NP)*VC
                         : v_template;
        if (gc + 3 < VC) {
            float2 u = *(const float2*)(src + gc);
            float2 w = *(const float2*)(src + gc + 2);
            val.x = u.x; val.y = u.y; val.z = w.x; val.w = w.y;
        } else {
            if (gc + 0 < VC) val.x = src[gc + 0];
            if (gc + 1 < VC) val.y = src[gc + 1];
            if (gc + 2 < VC) val.z = src[gc + 2];
        }
    }
    *(float4*)&g_P[(size_t)k*VCP + gc] = val;
}

// ---------------------------------------------------------------------------
// K1: Rodrigues -> rot output + duplicated factor matrix g_pft2
// ---------------------------------------------------------------------------
__global__ void k1_rodrigues(const float* __restrict__ inputs, float* __restrict__ out) {
    int g = blockIdx.x * blockDim.x + threadIdx.x;
    if (g >= NJ * B) return;
    int j = g / B;
    int b = g % B;
    float rx = inputs[b*82 + j*3 + 0];
    float ry = inputs[b*82 + j*3 + 1];
    float rz = inputs[b*82 + j*3 + 2];
    float ax = rx + 1e-8f, ay = ry + 1e-8f, az = rz + 1e-8f;
    float angle = sqrtf(ax*ax + ay*ay + az*az);
    float inv = 1.0f / angle;
    float nx = rx*inv, ny = ry*inv, nz = rz*inv;
    float c = cosf(angle), s = sinf(angle), oc = 1.0f - c;
    float R[9];
    R[0] = c + oc*nx*nx;    R[1] = oc*nx*ny - s*nz; R[2] = oc*nx*nz + s*ny;
    R[3] = oc*ny*nx + s*nz; R[4] = c + oc*ny*ny;    R[5] = oc*ny*nz - s*nx;
    R[6] = oc*nz*nx - s*ny; R[7] = oc*nz*ny + s*nx; R[8] = c + oc*nz*nz;
    float* ro = out + ROT_OFF + (size_t)b*216 + j*9;
#pragma unroll
    for (int m = 0; m < 9; m++) ro[m] = R[m];
    if (j > 0) {
        int base = (j-1)*9;
#pragma unroll
        for (int m = 0; m < 9; m++) {
            float idm = (m == 0 || m == 4 || m == 8) ? 1.0f : 0.0f;
            float val = R[m] - idm;
            g_pft2[(base + m)*1024 + b*2 + 0] = val;
            g_pft2[(base + m)*1024 + b*2 + 1] = val;
        }
    } else {
#pragma unroll
        for (int k = 0; k < 10; k++) {
            float val = inputs[b*82 + 72 + k];
            g_pft2[(NP + k)*1024 + b*2 + 0] = val;
            g_pft2[(NP + k)*1024 + b*2 + 1] = val;
        }
        g_pft2[217*1024 + b*2 + 0] = 1.0f;
        g_pft2[217*1024 + b*2 + 1] = 1.0f;
#pragma unroll
        for (int k = 218; k < KP; k++) {
            g_pft2[k*1024 + b*2 + 0] = 0.0f;
            g_pft2[k*1024 + b*2 + 1] = 0.0f;
        }
    }
}

// ---------------------------------------------------------------------------
// K2: Jdirs (shape basis + template regressed to joints) — coalesced
// ---------------------------------------------------------------------------
__global__ __launch_bounds__(256) void k2_jdirs(const float* __restrict__ v_template,
                         const float* __restrict__ shapes,
                         const float* __restrict__ smpl_reg) {
    __shared__ float spart[8][NJ];
    int k = blockIdx.x / 3;
    int c = blockIdx.x % 3;
    int tid = threadIdx.x;
    const float* src = (k < 10) ? (shapes + (size_t)k*VC) : v_template;
    float acc[NJ];
#pragma unroll
    for (int j = 0; j < NJ; j++) acc[j] = 0.0f;
    for (int v = tid; v < V; v += 256) {
        float sv = src[v*3 + c];
        const float4* r = (const float4*)&smpl_reg[v*NJ];
#pragma unroll
        for (int q = 0; q < 6; q++) {
            float4 rv = r[q];
            acc[q*4+0] += sv * rv.x;
            acc[q*4+1] += sv * rv.y;
            acc[q*4+2] += sv * rv.z;
            acc[q*4+3] += sv * rv.w;
        }
    }
#pragma unroll
    for (int j = 0; j < NJ; j++) {
#pragma unroll
        for (int o = 16; o > 0; o >>= 1)
            acc[j] += __shfl_down_sync(0xffffffffu, acc[j], o);
    }
    int warp = tid >> 5, lane = tid & 31;
    if (lane == 0) {
#pragma unroll
        for (int j = 0; j < NJ; j++) spart[warp][j] = acc[j];
    }
    __syncthreads();
    if (tid < NJ) {
        float s = 0.0f;
#pragma unroll
        for (int w = 0; w < 8; w++) s += spart[w][tid];
        g_Jdirs[k*(NJ*3) + tid*3 + c] = s;
    }
}

// ---------------------------------------------------------------------------
// K3: per-batch kinematic chain -> g_A
//   All per-batch state in stride-33 smem ((e+t)%32 banks: conflict-free).
//   J ALSO in smem now (regs=255 spill fix). Jdirs read as broadcast LDG.
// ---------------------------------------------------------------------------
__global__ __launch_bounds__(32) void k3_chain(const float* __restrict__ inputs,
                                               const float* __restrict__ out) {
    __shared__ float sAw[288*33];      // 38.0KB  [e][t]
    __shared__ float sJ[72*33];        //  9.5KB  [e][t]
    int t = threadIdx.x;
    int b = blockIdx.x * 32 + t;

    float beta[10];
#pragma unroll
    for (int k = 0; k < 10; k++) beta[k] = inputs[b*82 + 72 + k];

    // J = Jdirs_template + sum_k beta_k * Jdirs_k  (Jdirs via broadcast LDG)
    for (int e = 0; e < 72; e++) {
        float a = g_Jdirs[10*72 + e];
#pragma unroll
        for (int k = 0; k < 10; k++) a += beta[k]*g_Jdirs[k*72 + e];
        sJ[e*33 + t] = a;
    }

    const float* rot = out + ROT_OFF + (size_t)b*216;

    // joint 0: world = [R0 | J0]
#pragma unroll
    for (int m = 0; m < 9; m++) sAw[m*33 + t] = rot[m];
    sAw[ 9*33 + t] = sJ[0*33 + t];
    sAw[10*33 + t] = sJ[1*33 + t];
    sAw[11*33 + t] = sJ[2*33 + t];

    const int parents[NJ] = {0,0,0,0,1,2,3,4,5,6,7,8,9,9,9,12,13,14,16,17,18,19,20,21};
#pragma unroll
    for (int j = 1; j < NJ; j++) {
        const int p = parents[j];
        float Rl[9];
#pragma unroll
        for (int m = 0; m < 9; m++) Rl[m] = rot[j*9 + m];
        float Rp[12];
#pragma unroll
        for (int e = 0; e < 12; e++) Rp[e] = sAw[(p*12 + e)*33 + t];
        float W[12];
#pragma unroll
        for (int r = 0; r < 3; r++)
#pragma unroll
            for (int cc = 0; cc < 3; cc++)
                W[r*3+cc] = Rp[r*3+0]*Rl[0*3+cc] + Rp[r*3+1]*Rl[1*3+cc] + Rp[r*3+2]*Rl[2*3+cc];
        float dx = sJ[(j*3+0)*33+t]-sJ[(p*3+0)*33+t];
        float dy = sJ[(j*3+1)*33+t]-sJ[(p*3+1)*33+t];
        float dz = sJ[(j*3+2)*33+t]-sJ[(p*3+2)*33+t];
#pragma unroll
        for (int r = 0; r < 3; r++)
            W[9+r] = Rp[r*3+0]*dx + Rp[r*3+1]*dy + Rp[r*3+2]*dz + Rp[9+r];
#pragma unroll
        for (int e = 0; e < 12; e++) sAw[(j*12 + e)*33 + t] = W[e];
    }

    // in-place convert world -> relative 3x4 rows
#pragma unroll
    for (int j = 0; j < NJ; j++) {
        float W[12];
#pragma unroll
        for (int e = 0; e < 12; e++) W[e] = sAw[(j*12 + e)*33 + t];
        float jx = sJ[(j*3+0)*33+t], jy = sJ[(j*3+1)*33+t], jz = sJ[(j*3+2)*33+t];
        float Ar[12];
#pragma unroll
        for (int r = 0; r < 3; r++) {
            Ar[r*4+0] = W[r*3+0];
            Ar[r*4+1] = W[r*3+1];
            Ar[r*4+2] = W[r*3+2];
            Ar[r*4+3] = W[9+r] - (W[r*3+0]*jx + W[r*3+1]*jy + W[r*3+2]*jz);
        }
#pragma unroll
        for (int e = 0; e < 12; e++) sAw[(j*12 + e)*33 + t] = Ar[e];
    }
    __syncwarp();

    // coalesced copy-out
    size_t base = (size_t)(blockIdx.x*32) * 288;
    for (int idx = t; idx < 32*288; idx += 32) {
        int bb = idx / 288, e = idx % 288;
        g_A[base + idx] = sAw[e*33 + bb];
    }
}

// ---------------------------------------------------------------------------
// K4a v2: v_posed GEMM  C[b][vc] = sum_k F[k][b] * P[k][vc]
//   Block tile 128b x 256vc; 256 threads: warp = 16-batch group (F loads are
//   warp-uniform BROADCAST), lane = vc chunks lane*4 and 128+lane*4 (each warp
//   LDS.128 covers 512B contiguous -> conflict-free). Thread tile 16b x 8vc.
//   GK=8 double-buffered cp.async; grid (81,4)=324 -> 1.09 waves.
// ---------------------------------------------------------------------------
#define GK 8
#define NKC (KP/GK)   // 28

__global__ __launch_bounds__(256, 2) void k4a_gemm() {
    __shared__ __align__(16) float sP[2][GK*256];   // 16KB
    __shared__ __align__(16) float sF[2][GK*256];   // 16KB (dup: 128b -> 256 floats)
    int tid = threadIdx.x;
    int lane = tid & 31;
    int wp = tid >> 5;              // 0..7: batch group of 16
    int n0 = blockIdx.x * 256;
    int b0 = blockIdx.y * 128;

    uint32_t spP0 = (uint32_t)__cvta_generic_to_shared(&sP[0][0]);
    uint32_t spF0 = (uint32_t)__cvta_generic_to_shared(&sF[0][0]);

    ull acc[16][4];
#pragma unroll
    for (int bi = 0; bi < 16; bi++)
#pragma unroll
        for (int ni = 0; ni < 4; ni++) acc[bi][ni] = 0ull;

    auto stage = [&](int kc, int s) {
        uint32_t pb = spP0 + s*(GK*256*4);
        uint32_t fb = spF0 + s*(GK*256*4);
#pragma unroll
        for (int r = 0; r < 2; r++) {
            int i = tid + r*256;            // 0..511 float4s
            int row = i >> 6, c4 = i & 63;
            cpasync16(pb + (row*256 + c4*4)*4,
                      &g_P[(size_t)(kc*GK + row)*VCP + n0 + c4*4]);
        }
#pragma unroll
        for (int r = 0; r < 2; r++) {
            int i = tid + r*256;
            int row = i >> 6, c4 = i & 63;
            cpasync16(fb + (row*256 + c4*4)*4,
                      &g_pft2[(kc*GK + row)*1024 + b0*2 + c4*4]);
        }
        asm volatile("cp.async.commit_group;");
    };

    stage(0, 0);
    for (int kc = 0; kc < NKC; kc++) {
        int s = kc & 1;
        if (kc + 1 < NKC) stage(kc + 1, s ^ 1);
        else asm volatile("cp.async.commit_group;");
        asm volatile("cp.async.wait_group 1;");
        __syncthreads();
        const float* Pb = &sP[s][0];
        const float* Fb = &sF[s][0];
#pragma unroll
        for (int kk = 0; kk < GK; kk++) {
            // P: 2 conflict-free LDS.128 (warp covers 512B contiguous each)
            ulonglong2 pA = *(const ulonglong2*)&Pb[kk*256 + lane*4];
            ulonglong2 pB = *(const ulonglong2*)&Pb[kk*256 + 128 + lane*4];
            ull p0 = pA.x, p1 = pA.y, p2 = pB.x, p3 = pB.y;
            // F: 8 warp-uniform broadcast LDS.128 -> 16 dup-packed b-factors
            ull f[16];
#pragma unroll
            for (int q = 0; q < 8; q++) {
                ulonglong2 tq = *(const ulonglong2*)&Fb[kk*256 + wp*32 + q*4];
                f[q*2] = tq.x; f[q*2+1] = tq.y;
            }
#pragma unroll
            for (int bi = 0; bi < 16; bi++) {
                ffma2(acc[bi][0], f[bi], p0);
                ffma2(acc[bi][1], f[bi], p1);
                ffma2(acc[bi][2], f[bi], p2);
                ffma2(acc[bi][3], f[bi], p3);
            }
        }
        __syncthreads();
    }
#pragma unroll
    for (int bi = 0; bi < 16; bi++) {
        float* dst = &g_vposed[(size_t)(b0 + wp*16 + bi)*VCP + n0];
        ulonglong2 sA; sA.x = acc[bi][0]; sA.y = acc[bi][1];
        *(ulonglong2*)(dst + lane*4) = sA;
        ulonglong2 sB; sB.x = acc[bi][2]; sB.y = acc[bi][3];
        *(ulonglong2*)(dst + 128 + lane*4) = sB;
    }
}

// ---------------------------------------------------------------------------
// K4b: skinning. Block tile: 16 batches (8 f32x2 pairs) x 64 verts.
// ---------------------------------------------------------------------------
#define ST_VT 64
#define ST_BT 16

__global__ __launch_bounds__(256) void k4b_skin(
    const float* __restrict__ lbs, float* __restrict__ out)
{
    __shared__ __align__(16) float sA2[8*288*2];  // 18KB pair-interleaved
    __shared__ float sW[ST_VT*25];
    int tid = threadIdx.x;
    int v0 = blockIdx.x * ST_VT;
    int b0 = blockIdx.y * ST_BT;

    for (int i = tid; i < 8*2*288; i += 256) {
        int p = i / 576; int rem = i % 576; int h = rem / 288; int r = rem % 288;
        sA2[(p*288 + r)*2 + h] = g_A[(size_t)(b0 + 2*p + h)*288 + r];
    }
    for (int i = tid; i < ST_VT*NJ; i += 256) {
        int vl = i / NJ; int j = i % NJ;
        int v = v0 + vl;
        sW[vl*25 + j] = (v < V) ? lbs[v*NJ + j] : 0.0f;
    }
    __syncthreads();

    int p  = tid >> 5;
    int vt = tid & 31;

    ull T[2][12];
#pragma unroll
    for (int vi = 0; vi < 2; vi++)
#pragma unroll
        for (int e = 0; e < 12; e++) T[vi][e] = 0ull;

    const float* Ap = sA2 + p*576;
#pragma unroll
    for (int j = 0; j < NJ; j++) {
        ull a[12];
#pragma unroll
        for (int e2 = 0; e2 < 6; e2++) {
            ulonglong2 t = *(ulonglong2*)&Ap[(j*12 + e2*2)*2];
            a[e2*2] = t.x; a[e2*2+1] = t.y;
        }
#pragma unroll
        for (int vi = 0; vi < 2; vi++) {
            float w = sW[(vt + vi*32)*25 + j];
            ull ww = pack2(w, w);
#pragma unroll
            for (int e = 0; e < 12; e++) ffma2(T[vi][e], ww, a[e]);
        }
    }

#pragma unroll
    for (int vi = 0; vi < 2; vi++) {
        int v = v0 + vt + vi*32;
        if (v >= V) continue;
        float Ta[12], Tb[12];
#pragma unroll
        for (int e = 0; e < 12; e++) unpack2(T[vi][e], Ta[e], Tb[e]);
        {
            int b = b0 + 2*p;
            const float* hp = &g_vposed[(size_t)b*VCP + v*3];
            float vx = hp[0], vy = hp[1], vz = hp[2];
            float* o = out + VERT_OFF + ((size_t)b*V + v)*3;
            o[0] = Ta[0]*vx + Ta[1]*vy + Ta[2]*vz  + Ta[3];
            o[1] = Ta[4]*vx + Ta[5]*vy + Ta[6]*vz  + Ta[7];
            o[2] = Ta[8]*vx + Ta[9]*vy + Ta[10]*vz + Ta[11];
        }
        {
            int b = b0 + 2*p + 1;
            const float* hp = &g_vposed[(size_t)b*VCP + v*3];
            float vx = hp[0], vy = hp[1], vz = hp[2];
            float* o = out + VERT_OFF + ((size_t)b*V + v)*3;
            o[0] = Tb[0]*vx + Tb[1]*vy + Tb[2]*vz  + Tb[3];
            o[1] = Tb[4]*vx + Tb[5]*vy + Tb[6]*vz  + Tb[7];
            o[2] = Tb[8]*vx + Tb[9]*vy + Tb[10]*vz + Tb[11];
        }
    }
}

// ---------------------------------------------------------------------------
// K5: joints = regressor^T @ vertices — 8 batches per block (one per warp)
// ---------------------------------------------------------------------------
__global__ __launch_bounds__(256) void k5_joints(const float* __restrict__ jreg,
                                                 float* __restrict__ out)
{
    __shared__ float sreg[128*21];   // 10.8KB
    int tid = threadIdx.x;
    int warp = tid >> 5, lane = tid & 31;
    int b = blockIdx.x*8 + warp;
    const float* verts = out + VERT_OFF + (size_t)b*V*3;
    float acc[NJO*3];
#pragma unroll
    for (int e = 0; e < NJO*3; e++) acc[e] = 0.0f;

    for (int base = 0; base < V; base += 128) {
        __syncthreads();
        for (int i = tid; i < 128*NJO; i += 256) {
            int rr = i / NJO, j = i % NJO;
            int row = base + rr;
            sreg[rr*21 + j] = (row < V) ? jreg[row*NJO + j] : 0.0f;
        }
        __syncthreads();
#pragma unroll
        for (int vv = 0; vv < 4; vv++) {
            int vl = vv*32 + lane;
            int v = base + vl;
            if (v < V) {
                float px = verts[v*3+0], py = verts[v*3+1], pz = verts[v*3+2];
#pragma unroll
                for (int j = 0; j < NJO; j++) {
                    float r = sreg[vl*21 + j];
                    acc[j*3+0] += r*px;
                    acc[j*3+1] += r*py;
                    acc[j*3+2] += r*pz;
                }
            }
        }
    }
#pragma unroll
    for (int e = 0; e < NJO*3; e++) {
#pragma unroll
        for (int o = 16; o > 0; o >>= 1)
            acc[e] += __shfl_down_sync(0xffffffffu, acc[e], o);
    }
    if (lane == 0) {
#pragma unroll
        for (int e = 0; e < NJO*3; e++)
            out[JNT_OFF + b*(NJO*3) + e] = acc[e];
    }
}

// ---------------------------------------------------------------------------
extern "C" void kernel_launch(void* const* d_in, const int* in_sizes, int n_in,
                              void* d_out, int out_size) {
    const float* inputs     = (const float*)d_in[0];
    const float* v_template = (const float*)d_in[1];
    const float* shapes     = (const float*)d_in[2];
    const float* posedirs   = (const float*)d_in[3];
    const float* smpl_reg   = (const float*)d_in[4];
    const float* lbs        = (const float*)d_in[5];
    const float* jreg       = (const float*)d_in[6];
    float* out = (float*)d_out;

    k0_pack<<<(KP*(VCP/4) + 255)/256, 256>>>(posedirs, shapes, v_template);
    k1_rodrigues<<<(NJ*B + 255)/256, 256>>>(inputs, out);
    k2_jdirs<<<33, 256>>>(v_template, shapes, smpl_reg);
    k3_chain<<<B/32, 32>>>(inputs, out);
    dim3 ga(VCP/256, B/128);                    // (81, 4)
    k4a_gemm<<<ga, 256>>>();
    dim3 gb((V + ST_VT - 1)/ST_VT, B/ST_BT);    // (108, 32)
    k4b_skin<<<gb, 256>>>(lbs, out);
    k5_joints<<<B/8, 256>>>(jreg, out);
}